// round 2
// baseline (speedup 1.0000x reference)
#include <cuda_runtime.h>
#include <cuda_fp16.h>
#include <cstdint>

#define BATCH 32
#define T_LEN 2048
#define S_DIM 512
#define E_DIM 32
#define SLICES 4          // CTAs per batch (cluster size)
#define COLS 128          // output columns per CTA
#define NTHREADS 512
#define NWARPS 16
#define KCHUNK 32         // K range per warp (16 warps * 32 = 512)
#define ALPHA_SCALE 256.0f

// obs index per (batch, t) extracted from one-hot inputs
__device__ int g_obs[BATCH * T_LEN];

__global__ void obs_extract_kernel(const float* __restrict__ inputs) {
    int idx = blockIdx.x * blockDim.x + threadIdx.x;
    if (idx >= BATCH * T_LEN) return;
    const float* p = inputs + (size_t)idx * E_DIM;
    int e = 0;
#pragma unroll
    for (int i = 0; i < E_DIM; i++) {
        if (p[i] > 0.5f) e = i;
    }
    g_obs[idx] = e;
}

__device__ __forceinline__ uint32_t smem_u32(const void* p) {
    uint32_t a;
    asm("{ .reg .u64 t; cvta.to.shared.u64 t, %1; cvt.u32.u64 %0, t; }"
        : "=r"(a) : "l"(p));
    return a;
}

__device__ __forceinline__ void cluster_sync_() {
    asm volatile("barrier.cluster.arrive.aligned;" ::: "memory");
    asm volatile("barrier.cluster.wait.aligned;" ::: "memory");
}

__device__ __forceinline__ void st_cluster_f32(uint32_t saddr, uint32_t rank, float v) {
    uint32_t ra;
    asm volatile("mapa.shared::cluster.u32 %0, %1, %2;" : "=r"(ra) : "r"(saddr), "r"(rank));
    asm volatile("st.shared::cluster.f32 [%0], %1;" :: "r"(ra), "f"(v) : "memory");
}

__global__ void __cluster_dims__(SLICES, 1, 1) __launch_bounds__(NTHREADS, 1)
hmm_forward_kernel(const float* __restrict__ A,
                   const float* __restrict__ Bem,
                   const float* __restrict__ pi,
                   float* __restrict__ out)
{
    __shared__ __half2 alpha_s[S_DIM];       // {a,a} duplicated halves, 2KB
    __shared__ float   valbuf[2][S_DIM];     // double-buffered full alpha exchange, 4KB
    __shared__ float   bem_t[E_DIM][COLS];   // emission slice transposed, 16KB
    __shared__ float   part[NWARPS][COLS];   // per-warp K-chunk partials, 8KB
    __shared__ float   zred[NWARPS];
    __shared__ int     obs_s[T_LEN];         // 8KB obs row for this batch

    const int tid = threadIdx.x;
    const int w = tid >> 5;
    const int l = tid & 31;
    uint32_t crank;
    asm("mov.u32 %0, %%cluster_ctarank;" : "=r"(crank));
    const int c = (int)crank;           // slice index 0..3
    const int b = blockIdx.x / SLICES;  // batch

    // ---- Load A slice into registers as fp16x2 (persistent across all steps) ----
    // thread (w,l): rows k in [32w, 32w+32), columns j = c*128 + 4l + {0..3}
    __half2 a2[KCHUNK][2];
    {
        const float4* Ag = reinterpret_cast<const float4*>(
            A + (size_t)(w * KCHUNK) * S_DIM + c * COLS + 4 * l);
#pragma unroll
        for (int kk = 0; kk < KCHUNK; kk++) {
            float4 v = Ag[kk * (S_DIM / 4)];
            a2[kk][0] = __floats2half2_rn(v.x, v.y);
            a2[kk][1] = __floats2half2_rn(v.z, v.w);
        }
    }

    // ---- Emission slice: bem_t[e][jl] = Bem[(c*128+jl)*E + e] ----
    for (int i = tid; i < E_DIM * COLS; i += NTHREADS) {
        int e = i / COLS, jl = i % COLS;
        bem_t[e][jl] = Bem[(size_t)(c * COLS + jl) * E_DIM + e];
    }
    // ---- obs row for this batch into smem ----
    for (int i = tid; i < T_LEN; i += NTHREADS) obs_s[i] = g_obs[b * T_LEN + i];

    __syncthreads();
    cluster_sync_();  // peers initialized before any DSMEM traffic

    const uint32_t valbuf_sa = smem_u32(&valbuf[0][0]);

    float lg2sum = 0.0f;   // sum of log2(z_raw)
    int buf = 0;

    for (int t = 0; t < T_LEN; t++) {
        const int e = obs_s[t];
        float myval = 0.0f;

        if (t == 0) {
            if (tid < COLS) {
                myval = pi[c * COLS + tid] * bem_t[e][tid];
            }
        } else {
            // ---- matvec slice: pre[j] = sum_k alpha[k] * A[k][j] ----
            __half2 acc0 = __float2half2_rn(0.0f);
            __half2 acc1 = acc0;
            const int kbase = w * KCHUNK;
#pragma unroll
            for (int kk = 0; kk < KCHUNK; kk++) {
                __half2 av = alpha_s[kbase + kk];   // broadcast LDS
                acc0 = __hfma2(av, a2[kk][0], acc0);
                acc1 = __hfma2(av, a2[kk][1], acc1);
            }
            float2 f0 = __half22float2(acc0);
            float2 f1 = __half22float2(acc1);
            float4 pv = make_float4(f0.x, f0.y, f1.x, f1.y);
            *reinterpret_cast<float4*>(&part[w][4 * l]) = pv;
            __syncthreads();

            if (tid < COLS) {
                float s = 0.0f;
#pragma unroll
                for (int ww = 0; ww < NWARPS; ww++) s += part[ww][tid];
                myval = s * bem_t[e][tid];
            }
        }

        // ---- scatter my 128 vals into all 4 CTAs' valbuf[buf] ----
        if (tid < COLS) {
            uint32_t off = valbuf_sa + (uint32_t)(buf * S_DIM + c * COLS + tid) * 4u;
#pragma unroll
            for (int r = 0; r < SLICES; r++) st_cluster_f32(off, (uint32_t)r, myval);
        }
        cluster_sync_();

        // ---- z = sum over all 512 vals; normalize into alpha_s (scaled x256) ----
        float v = valbuf[buf][tid];
        float zs = v;
#pragma unroll
        for (int o = 16; o > 0; o >>= 1) zs += __shfl_xor_sync(0xffffffffu, zs, o);
        if (l == 0) zred[w] = zs;
        __syncthreads();
        float z = 0.0f;
#pragma unroll
        for (int i = 0; i < NWARPS; i++) z += zred[i];

        float rz = ALPHA_SCALE / z;
        alpha_s[tid] = __float2half2_rn(v * rz);
        lg2sum += __log2f(z);
        buf ^= 1;
        __syncthreads();
    }

    if (c == 0 && tid == 0) {
        // steps 1..T-1 carried an extra factor 256 in z_raw: subtract (T-1)*log2(256)=8
        float loglik = (lg2sum - (float)(T_LEN - 1) * 8.0f) * 0.6931471805599453f;
        out[b] = loglik;
    }
    cluster_sync_();
}

extern "C" void kernel_launch(void* const* d_in, const int* in_sizes, int n_in,
                              void* d_out, int out_size)
{
    const float* inputs = (const float*)d_in[0];  // [B,T,E] one-hot
    const float* A      = (const float*)d_in[1];  // [S,S]
    const float* Bem    = (const float*)d_in[2];  // [S,E]
    const float* pi     = (const float*)d_in[3];  // [S]
    float* out = (float*)d_out;                   // [B]

    obs_extract_kernel<<<(BATCH * T_LEN + 255) / 256, 256>>>(inputs);
    hmm_forward_kernel<<<BATCH * SLICES, NTHREADS>>>(A, Bem, pi, out);
}

// round 4
// speedup vs baseline: 1.3308x; 1.3308x over previous
#include <cuda_runtime.h>
#include <cuda_fp16.h>
#include <cstdint>

#define BATCH 32
#define T_LEN 2048
#define S_DIM 512
#define E_DIM 32
#define SLICES 4          // CTAs per batch (cluster size)
#define COLS 128          // output columns per CTA
#define NTHREADS 512
#define NWARPS 16
#define KCHUNK 32         // K range per warp (16 warps * 32 = 512)
#define ALPHA_SCALE 256.0f
// per-step tx into each CTA: 4 slices * (128 vals + 4 z-partials) * 4B
#define STEP_TX_BYTES ((SLICES * (COLS + 4)) * 4)

__device__ int g_obs[BATCH * T_LEN];

__global__ void obs_extract_kernel(const float* __restrict__ inputs) {
    int idx = blockIdx.x * blockDim.x + threadIdx.x;
    if (idx >= BATCH * T_LEN) return;
    const float* p = inputs + (size_t)idx * E_DIM;
    int e = 0;
#pragma unroll
    for (int i = 0; i < E_DIM; i++) {
        if (p[i] > 0.5f) e = i;
    }
    g_obs[idx] = e;
}

__device__ __forceinline__ uint32_t smem_u32(const void* p) {
    uint32_t a;
    asm("{ .reg .u64 t; cvta.to.shared.u64 t, %1; cvt.u32.u64 %0, t; }"
        : "=r"(a) : "l"(p));
    return a;
}

__device__ __forceinline__ uint32_t mapa_u32(uint32_t saddr, uint32_t rank) {
    uint32_t ra;
    asm("mapa.shared::cluster.u32 %0, %1, %2;" : "=r"(ra) : "r"(saddr), "r"(rank));
    return ra;
}

__device__ __forceinline__ void cluster_sync_() {
    asm volatile("barrier.cluster.arrive.aligned;" ::: "memory");
    asm volatile("barrier.cluster.wait.aligned;" ::: "memory");
}

// async store of 4 bytes into (remote) cluster smem with tx accounting
__device__ __forceinline__ void st_async_b32(uint32_t raddr, float v, uint32_t rmbar) {
    asm volatile(
        "st.async.shared::cluster.mbarrier::complete_tx::bytes.b32 [%0], %1, [%2];"
        :: "r"(raddr), "r"(__float_as_uint(v)), "r"(rmbar) : "memory");
}

__device__ __forceinline__ void mbar_init(uint32_t mbar, uint32_t cnt) {
    asm volatile("mbarrier.init.shared.b64 [%0], %1;" :: "r"(mbar), "r"(cnt) : "memory");
}

__device__ __forceinline__ void mbar_expect_tx(uint32_t mbar, uint32_t bytes) {
    asm volatile("mbarrier.arrive.expect_tx.shared.b64 _, [%0], %1;"
                 :: "r"(mbar), "r"(bytes) : "memory");
}

__device__ __forceinline__ void mbar_wait_parity(uint32_t mbar, uint32_t parity) {
    asm volatile(
        "{\n\t"
        ".reg .pred P;\n\t"
        "WAIT_%=: \n\t"
        "mbarrier.try_wait.parity.acquire.cluster.shared::cta.b64 P, [%0], %1, 0x989680;\n\t"
        "@!P bra WAIT_%=;\n\t"
        "}"
        :: "r"(mbar), "r"(parity) : "memory");
}

__device__ __forceinline__ float warp_sum32(float v) {
#pragma unroll
    for (int o = 16; o > 0; o >>= 1)
        v += __shfl_xor_sync(0xffffffffu, v, o);
    return v;
}

__global__ void __cluster_dims__(SLICES, 1, 1) __launch_bounds__(NTHREADS, 1)
hmm_forward_kernel(const float* __restrict__ A,
                   const float* __restrict__ Bem,
                   const float* __restrict__ pi,
                   float* __restrict__ out)
{
    __shared__ __half2 alpha_s[S_DIM];           // {a,a} duplicated halves
    __shared__ float   valbuf[2][S_DIM];         // double-buffered alpha exchange
    __shared__ float   zbuf[2][SLICES * 4];      // per-warp z partials, 4/slice
    __shared__ float   bem_t[E_DIM][COLS];       // emission slice transposed
    __shared__ float   part[NWARPS][COLS];       // per-warp K-chunk partials
    __shared__ int     obs_s[T_LEN];
    __shared__ __align__(8) unsigned long long mbar_store[2];

    const int tid = threadIdx.x;
    const int w = tid >> 5;
    const int l = tid & 31;
    uint32_t crank;
    asm("mov.u32 %0, %%cluster_ctarank;" : "=r"(crank));
    const int c = (int)crank;
    const int b = blockIdx.x / SLICES;

    // ---- A slice into registers as fp16x2 (persistent) ----
    __half2 a2[KCHUNK][2];
    {
        const float4* Ag = reinterpret_cast<const float4*>(
            A + (size_t)(w * KCHUNK) * S_DIM + c * COLS + 4 * l);
#pragma unroll
        for (int kk = 0; kk < KCHUNK; kk++) {
            float4 v = Ag[kk * (S_DIM / 4)];
            a2[kk][0] = __floats2half2_rn(v.x, v.y);
            a2[kk][1] = __floats2half2_rn(v.z, v.w);
        }
    }

    for (int i = tid; i < E_DIM * COLS; i += NTHREADS) {
        int e = i / COLS, jl = i % COLS;
        bem_t[e][jl] = Bem[(size_t)(c * COLS + jl) * E_DIM + e];
    }
    for (int i = tid; i < T_LEN; i += NTHREADS) obs_s[i] = g_obs[b * T_LEN + i];

    const uint32_t val_sa  = smem_u32(&valbuf[0][0]);
    const uint32_t z_sa    = smem_u32(&zbuf[0][0]);
    const uint32_t mbar_sa = smem_u32(&mbar_store[0]);

    if (tid == 0) {
        mbar_init(mbar_sa, 1);
        mbar_init(mbar_sa + 8, 1);
    }
    __syncthreads();
    cluster_sync_();   // one-time: peers' mbarriers + smem init visible

    // hoisted remote base addresses (one mapa set for the whole kernel)
    uint32_t val_r[SLICES], z_r[SLICES], mb_r[SLICES];
#pragma unroll
    for (int r = 0; r < SLICES; r++) {
        val_r[r] = mapa_u32(val_sa, (uint32_t)r);
        z_r[r]   = mapa_u32(z_sa, (uint32_t)r);
        mb_r[r]  = mapa_u32(mbar_sa, (uint32_t)r);
    }

    // ---- PROLOGUE: produce step 0 into buf 0 ----
    {
        const int e0 = obs_s[0];
        if (tid < COLS) {
            float myval = pi[c * COLS + tid] * bem_t[e0][tid];
            uint32_t voff = (uint32_t)((c * COLS + tid) * 4);
#pragma unroll
            for (int r = 0; r < SLICES; r++)
                st_async_b32(val_r[r] + voff, myval, mb_r[r]);
            float zs = warp_sum32(myval);
            if (l == 0) {
                uint32_t zoff = (uint32_t)((c * 4 + w) * 4);
#pragma unroll
                for (int r = 0; r < SLICES; r++)
                    st_async_b32(z_r[r] + zoff, zs, mb_r[r]);
            }
        }
    }

    float lg2sum = 0.0f;

    for (int t = 0; t < T_LEN; t++) {
        const int buf = t & 1;
        const uint32_t parity = (uint32_t)((t >> 1) & 1);
        const uint32_t mbar_l = mbar_sa + buf * 8;

        if (tid == 0) mbar_expect_tx(mbar_l, STEP_TX_BYTES);
        mbar_wait_parity(mbar_l, parity);

        // z computed redundantly by every thread (16 broadcast LDS + tree add)
        float z = 0.0f;
#pragma unroll
        for (int i = 0; i < SLICES * 4; i++) z += zbuf[buf][i];

        float v = valbuf[buf][tid];
        float rz = ALPHA_SCALE / z;
        alpha_s[tid] = __float2half2_rn(v * rz);
        lg2sum += __log2f(z);
        __syncthreads();   // alpha_s ready (also protects valbuf reuse ordering)

        if (t + 1 < T_LEN) {
            const int e = obs_s[t + 1];
            const int nbuf = buf ^ 1;

            // ---- matvec slice ----
            __half2 acc0 = __float2half2_rn(0.0f);
            __half2 acc1 = acc0;
            const int kbase = w * KCHUNK;
#pragma unroll
            for (int kk = 0; kk < KCHUNK; kk++) {
                __half2 av = alpha_s[kbase + kk];
                acc0 = __hfma2(av, a2[kk][0], acc0);
                acc1 = __hfma2(av, a2[kk][1], acc1);
            }
            float2 f0 = __half22float2(acc0);
            float2 f1 = __half22float2(acc1);
            *reinterpret_cast<float4*>(&part[w][4 * l]) =
                make_float4(f0.x, f0.y, f1.x, f1.y);
            __syncthreads();   // part[][] ready

            if (tid < COLS) {
                float s = 0.0f;
#pragma unroll
                for (int ww = 0; ww < NWARPS; ww++) s += part[ww][tid];
                float myval = s * bem_t[e][tid];

                uint32_t voff = (uint32_t)((nbuf * S_DIM + c * COLS + tid) * 4);
#pragma unroll
                for (int r = 0; r < SLICES; r++)
                    st_async_b32(val_r[r] + voff, myval, mb_r[r] + nbuf * 8);

                float zs = warp_sum32(myval);
                if (l == 0) {
                    uint32_t zoff = (uint32_t)((nbuf * SLICES * 4 + c * 4 + w) * 4);
#pragma unroll
                    for (int r = 0; r < SLICES; r++)
                        st_async_b32(z_r[r] + zoff, zs, mb_r[r] + nbuf * 8);
                }
            }
        }
    }

    if (c == 0 && tid == 0) {
        // steps 1..T-1 carried an extra factor 256 in z_raw: log2(256)=8 each
        float loglik = (lg2sum - (float)(T_LEN - 1) * 8.0f) * 0.6931471805599453f;
        out[b] = loglik;
    }
    cluster_sync_();   // no CTA exits while peers may still target its smem
}

extern "C" void kernel_launch(void* const* d_in, const int* in_sizes, int n_in,
                              void* d_out, int out_size)
{
    const float* inputs = (const float*)d_in[0];  // [B,T,E] one-hot
    const float* A      = (const float*)d_in[1];  // [S,S]
    const float* Bem    = (const float*)d_in[2];  // [S,E]
    const float* pi     = (const float*)d_in[3];  // [S]
    float* out = (float*)d_out;                   // [B]

    obs_extract_kernel<<<(BATCH * T_LEN + 255) / 256, 256>>>(inputs);
    hmm_forward_kernel<<<BATCH * SLICES, NTHREADS>>>(A, Bem, pi, out);
}

// round 5
// speedup vs baseline: 1.6954x; 1.2739x over previous
#include <cuda_runtime.h>
#include <cuda_fp16.h>
#include <cstdint>

#define BATCH 32
#define T_LEN 2048
#define S_DIM 512
#define E_DIM 32
#define SLICES 4          // CTAs per batch (cluster size)
#define COLS 128          // output columns per CTA
#define NTHREADS 512
#define TARGET_EXP 6      // keep sum(w) ~ 2^6
#define VBYTES (SLICES * 64 * 4)   // 4 slices x 64 half2 words
#define ZBYTES (SLICES * 2 * 4)    // 4 slices x 2 fp32 partials

__device__ int g_obs[BATCH * T_LEN];

__global__ void obs_extract_kernel(const float* __restrict__ inputs) {
    int idx = blockIdx.x * blockDim.x + threadIdx.x;
    if (idx >= BATCH * T_LEN) return;
    const float* p = inputs + (size_t)idx * E_DIM;
    int e = 0;
#pragma unroll
    for (int i = 0; i < E_DIM; i++) {
        if (p[i] > 0.5f) e = i;
    }
    g_obs[idx] = e;
}

__device__ __forceinline__ uint32_t smem_u32(const void* p) {
    uint32_t a;
    asm("{ .reg .u64 t; cvta.to.shared.u64 t, %1; cvt.u32.u64 %0, t; }"
        : "=r"(a) : "l"(p));
    return a;
}

__device__ __forceinline__ uint32_t mapa_u32(uint32_t saddr, uint32_t rank) {
    uint32_t ra;
    asm("mapa.shared::cluster.u32 %0, %1, %2;" : "=r"(ra) : "r"(saddr), "r"(rank));
    return ra;
}

__device__ __forceinline__ void cluster_sync_() {
    asm volatile("barrier.cluster.arrive.aligned;" ::: "memory");
    asm volatile("barrier.cluster.wait.aligned;" ::: "memory");
}

__device__ __forceinline__ void st_async_u32(uint32_t raddr, uint32_t v, uint32_t rmbar) {
    asm volatile(
        "st.async.shared::cluster.mbarrier::complete_tx::bytes.b32 [%0], %1, [%2];"
        :: "r"(raddr), "r"(v), "r"(rmbar) : "memory");
}

__device__ __forceinline__ void mbar_init(uint32_t mbar, uint32_t cnt) {
    asm volatile("mbarrier.init.shared.b64 [%0], %1;" :: "r"(mbar), "r"(cnt) : "memory");
}

__device__ __forceinline__ void mbar_expect_tx(uint32_t mbar, uint32_t bytes) {
    asm volatile("mbarrier.arrive.expect_tx.shared.b64 _, [%0], %1;"
                 :: "r"(mbar), "r"(bytes) : "memory");
}

__device__ __forceinline__ void mbar_wait_parity(uint32_t mbar, uint32_t parity) {
    asm volatile(
        "{\n\t"
        ".reg .pred P;\n\t"
        "WAIT_%=: \n\t"
        "mbarrier.try_wait.parity.acquire.cluster.shared::cta.b64 P, [%0], %1, 0x989680;\n\t"
        "@!P bra WAIT_%=;\n\t"
        "}"
        :: "r"(mbar), "r"(parity) : "memory");
}

__device__ __forceinline__ float warp_sum32(float v) {
#pragma unroll
    for (int o = 16; o > 0; o >>= 1)
        v += __shfl_xor_sync(0xffffffffu, v, o);
    return v;
}

__global__ void __cluster_dims__(SLICES, 1, 1) __launch_bounds__(NTHREADS, 1)
hmm_forward_kernel(const float* __restrict__ A,
                   const float* __restrict__ Bem,
                   const float* __restrict__ pi,
                   float* __restrict__ out)
{
    __shared__ uint32_t alpha2[2][S_DIM / 2];   // packed half2 {w[2m], w[2m+1]}
    __shared__ float    zbuf[2][SLICES * 2];    // fp32 sum partials (2 per slice)
    __shared__ float    bem_t[E_DIM][COLS];     // emission slice transposed
    __shared__ float    part[4][COLS];          // per-K-chunk partials
    __shared__ float    embias[E_DIM];          // mean emission per symbol
    __shared__ int      obs_s[T_LEN];
    __shared__ __align__(8) unsigned long long mbar_store[4]; // v0,v1,z0,z1

    const int tid = threadIdx.x;
    const int w = tid >> 5;
    const int l = tid & 31;
    const int kc = w >> 2;      // K-chunk 0..3 (rows 128*kc .. +128)
    const int cg = w & 3;       // col-group 0..3 (cols 32*cg .. +32)
    uint32_t crank;
    asm("mov.u32 %0, %%cluster_ctarank;" : "=r"(crank));
    const int c = (int)crank;
    const int b = blockIdx.x / SLICES;

    // ---- A slice into registers: a2[p] = {A[128kc+2p][jg], A[128kc+2p+1][jg]} ----
    const int jg = c * COLS + cg * 32 + l;   // global output column
    __half2 a2[64];
#pragma unroll
    for (int p = 0; p < 64; p++) {
        float r0 = A[(size_t)(128 * kc + 2 * p) * S_DIM + jg];
        float r1 = A[(size_t)(128 * kc + 2 * p + 1) * S_DIM + jg];
        a2[p] = __floats2half2_rn(r0, r1);
    }

    for (int i = tid; i < E_DIM * COLS; i += NTHREADS) {
        int e = i / COLS, jl = i % COLS;
        bem_t[e][jl] = Bem[(size_t)(c * COLS + jl) * E_DIM + e];
    }
    for (int i = tid; i < T_LEN; i += NTHREADS) obs_s[i] = g_obs[b * T_LEN + i];

    // ---- per-symbol mean emission (for lagged scale estimate) ----
    {
        int e = tid >> 4, seg = tid & 15;
        float s = 0.0f;
#pragma unroll 4
        for (int i = 0; i < 32; i++)
            s += Bem[(size_t)(seg * 32 + i) * E_DIM + e];
#pragma unroll
        for (int o = 8; o > 0; o >>= 1)
            s += __shfl_xor_sync(0xffffffffu, s, o);
        if (seg == 0) embias[e] = s * (1.0f / 512.0f);
    }

    const uint32_t val_sa  = smem_u32(&alpha2[0][0]);
    const uint32_t z_sa    = smem_u32(&zbuf[0][0]);
    const uint32_t mbar_sa = smem_u32(&mbar_store[0]);

    if (tid == 0) {
#pragma unroll
        for (int i = 0; i < 4; i++) mbar_init(mbar_sa + i * 8, 1);
    }
    __syncthreads();
    cluster_sync_();   // peers' mbarriers + smem ready before any st.async

    uint32_t val_r[SLICES], z_r[SLICES], mb_r[SLICES];
#pragma unroll
    for (int r = 0; r < SLICES; r++) {
        val_r[r] = mapa_u32(val_sa, (uint32_t)r);
        z_r[r]   = mapa_u32(z_sa, (uint32_t)r);
        mb_r[r]  = mapa_u32(mbar_sa, (uint32_t)r);
    }
    // mbar offsets: v[buf] = buf*8 ; z[buf] = 16 + buf*8

    // ---- PROLOGUE: produce w_0 = 2^TARGET * pi .* em_0 into buf 0 ----
    if (tid < 64) {
        const int e0 = obs_s[0];
        float2 pp = *reinterpret_cast<const float2*>(&pi[c * COLS + 2 * tid]);
        float2 bm = *reinterpret_cast<const float2*>(&bem_t[e0][2 * tid]);
        const float sc0 = (float)(1 << TARGET_EXP);
        float m0 = pp.x * bm.x * sc0;
        float m1 = pp.y * bm.y * sc0;
        __half2 h = __floats2half2_rn(m0, m1);
        uint32_t hv = *reinterpret_cast<uint32_t*>(&h);
        uint32_t voff = (uint32_t)((c * 64 + tid) * 4);
#pragma unroll
        for (int r = 0; r < SLICES; r++)
            st_async_u32(val_r[r] + voff, hv, mb_r[r] + 0);
        float zs = warp_sum32(m0 + m1);
        if (l == 0) {
            uint32_t zoff = (uint32_t)((c * 2 + w) * 4);
#pragma unroll
            for (int r = 0; r < SLICES; r++)
                st_async_u32(z_r[r] + zoff, __float_as_uint(zs), mb_r[r] + 16);
        }
    }

    int   K = TARGET_EXP;   // accumulated power-of-2 exponents (exact)
    float scale = 1.0f;
    int   en = 0;

    for (int t = 0; t < T_LEN - 1; t++) {
        const int buf = t & 1;
        const int nbuf = buf ^ 1;
        const uint32_t par = (uint32_t)((t >> 1) & 1);

        if (tid == 0) {
            mbar_expect_tx(mbar_sa + buf * 8, VBYTES);
            mbar_expect_tx(mbar_sa + 16 + buf * 8, ZBYTES);
        }

        // warps 0-1: pick up last step's sum, choose next scale (off matvec path)
        if (tid < 64) {
            mbar_wait_parity(mbar_sa + 16 + buf * 8, par);
            float2 z0 = *reinterpret_cast<const float2*>(&zbuf[buf][0]);
            float2 z1 = *reinterpret_cast<const float2*>(&zbuf[buf][2]);
            float2 z2 = *reinterpret_cast<const float2*>(&zbuf[buf][4]);
            float2 z3 = *reinterpret_cast<const float2*>(&zbuf[buf][6]);
            float Z = ((z0.x + z0.y) + (z1.x + z1.y)) + ((z2.x + z2.y) + (z3.x + z3.y));
            en = obs_s[t + 1];
            float Zm = Z * embias[en];
            int ex = ((__float_as_int(Zm) >> 23) & 255) - 127;
            int d = TARGET_EXP - ex;
            d = d < -48 ? -48 : (d > 48 ? 48 : d);
            scale = __int_as_float((uint32_t)(d + 127) << 23);
            K += d;
        }

        mbar_wait_parity(mbar_sa + buf * 8, par);   // values landed -> matvec

        __half2 acc0 = __float2half2_rn(0.0f);
        __half2 acc1 = acc0;
        const uint32_t* ab = &alpha2[buf][64 * kc];
#pragma unroll
        for (int m2 = 0; m2 < 32; m2++) {
            uint2 av = *reinterpret_cast<const uint2*>(&ab[2 * m2]);
            acc0 = __hfma2(*reinterpret_cast<__half2*>(&av.x), a2[2 * m2], acc0);
            acc1 = __hfma2(*reinterpret_cast<__half2*>(&av.y), a2[2 * m2 + 1], acc1);
        }
        float2 f0 = __half22float2(acc0);
        float2 f1 = __half22float2(acc1);
        part[kc][cg * 32 + l] = (f0.x + f0.y) + (f1.x + f1.y);
        __syncthreads();

        if (tid < 64) {
            float2 p0 = *reinterpret_cast<const float2*>(&part[0][2 * tid]);
            float2 p1 = *reinterpret_cast<const float2*>(&part[1][2 * tid]);
            float2 p2 = *reinterpret_cast<const float2*>(&part[2][2 * tid]);
            float2 p3 = *reinterpret_cast<const float2*>(&part[3][2 * tid]);
            float s0 = (p0.x + p1.x) + (p2.x + p3.x);
            float s1 = (p0.y + p1.y) + (p2.y + p3.y);
            float2 bm = *reinterpret_cast<const float2*>(&bem_t[en][2 * tid]);
            float m0 = s0 * bm.x * scale;
            float m1 = s1 * bm.y * scale;
            __half2 h = __floats2half2_rn(m0, m1);
            uint32_t hv = *reinterpret_cast<uint32_t*>(&h);
            uint32_t voff = (uint32_t)((nbuf * 256 + c * 64 + tid) * 4);
#pragma unroll
            for (int r = 0; r < SLICES; r++)
                st_async_u32(val_r[r] + voff, hv, mb_r[r] + nbuf * 8);
            float zs = warp_sum32(m0 + m1);
            if (l == 0) {
                uint32_t zoff = (uint32_t)((nbuf * 8 + c * 2 + w) * 4);
#pragma unroll
                for (int r = 0; r < SLICES; r++)
                    st_async_u32(z_r[r] + zoff, __float_as_uint(zs),
                                 mb_r[r] + 16 + nbuf * 8);
            }
        }
    }

    // ---- FINAL: consume w_{T-1}'s sum only ----
    {
        const int fbuf = (T_LEN - 1) & 1;
        const uint32_t fpar = (uint32_t)(((T_LEN - 1) >> 1) & 1);
        if (tid == 0) {
            mbar_expect_tx(mbar_sa + fbuf * 8, VBYTES);
            mbar_expect_tx(mbar_sa + 16 + fbuf * 8, ZBYTES);
        }
        mbar_wait_parity(mbar_sa + fbuf * 8, fpar);       // ensure all tx landed
        mbar_wait_parity(mbar_sa + 16 + fbuf * 8, fpar);
        if (c == 0 && tid == 0) {
            float Z = 0.0f;
#pragma unroll
            for (int i = 0; i < SLICES * 2; i++) Z += zbuf[fbuf][i];
            out[b] = (log2f(Z) - (float)K) * 0.6931471805599453f;
        }
    }
    cluster_sync_();   // no CTA exits while peers may still target its smem
}

extern "C" void kernel_launch(void* const* d_in, const int* in_sizes, int n_in,
                              void* d_out, int out_size)
{
    const float* inputs = (const float*)d_in[0];  // [B,T,E] one-hot
    const float* A      = (const float*)d_in[1];  // [S,S]
    const float* Bem    = (const float*)d_in[2];  // [S,E]
    const float* pi     = (const float*)d_in[3];  // [S]
    float* out = (float*)d_out;                   // [B]

    obs_extract_kernel<<<(BATCH * T_LEN + 255) / 256, 256>>>(inputs);
    hmm_forward_kernel<<<BATCH * SLICES, NTHREADS>>>(A, Bem, pi, out);
}